// round 17
// baseline (speedup 1.0000x reference)
#include <cuda_runtime.h>
#include <cuda_fp16.h>
#include <cuda_bf16.h>
#include <stdint.h>
#include <math.h>

#define BATCH 256
#define LIN   608
#define FLT   19
#define POOL  7
#define LP    84
#define HID   100
#define NU    300
#define NCLS  50
#define EPSV  1e-5f

#define MTILES 19              // 304 unit rows
#define KSTEPS 5               // conv K=80: 4 ch x 20 (kk=19 zero-padded in A)
#define WARPS  14
#define CTH    448
#define PPW    2               // pools per warp per round (pairs -> packed y)
#define ROUNDS 3               // 14*2*3 = 84 pools

#define MKS    6               // MLP K = 96 (84 padded), 6 ksteps
#define MNT    13              // MLP N = 104 (100 padded), 13 ntiles
#define W2FSL  (MNT * MKS * 2 * 32)   // uint2 per unit slice = 4992
#define W2TOT  (NU * W2FSL)           // 1497600 (= 256 * 5850)
#define W2SLC  (W2TOT / BATCH)        // 5850 items per conv CTA

#define FSPL   12              // final linear split factor (12 x 25 units)

typedef unsigned long long u64;

// scratch / precomputed (device globals; zero-initialized -> pads stay 0)
__device__ float  g_z[NU * BATCH];                    // [u][b]
__device__ __half g_A[MTILES * KSTEPS * 256];         // conv A, ldmatrix layout
__device__ float  g_s1[NU], g_c1[NU];
__device__ uint2  g_yA[(size_t)NU * BATCH * 48];      // y frags: [u][b][fp] {hi,lo}
__device__ uint2  g_w2f[(size_t)W2TOT];               // w2 frags {hi,lo}
__device__ float  g_part[FSPL * NCLS * BATCH];        // final split partials

// ---------------------------------------------------------------------------
// conv smem layout (dynamic):
// A 48640 | xt_even 4992 | xt_odd 4992 | y-staging 34048 | s1 1216 | c1 1216
// ---------------------------------------------------------------------------
#define SA     0
#define ASZ    (MTILES * KSTEPS * 512)   // 48640
#define SXT    ASZ                       // 48640
#define XTSZ   4992                      // 4 ch * 312 half2
#define SST    (SXT + 2 * XTSZ)          // 58624: staging [304][14] uint2
#define SSTSZ  (304 * 14 * 8)            // 34048
#define SBN_S  (SST + SSTSZ)             // 92672 (304 floats, padded)
#define SBN_C  (SBN_S + 1216)            // 93888
#define SMTOT  (SBN_C + 1216)            // 95104

__device__ __forceinline__ uint32_t smem_u32(const void* p) {
    uint32_t a;
    asm("{ .reg .u64 t; cvta.to.shared.u64 t, %1; cvt.u32.u64 %0, t; }"
        : "=r"(a) : "l"(p));
    return a;
}

#define LDSM4(r, a) \
    asm volatile("ldmatrix.sync.aligned.m8n8.x4.shared.b16 {%0,%1,%2,%3}, [%4];" \
        : "=r"((r)[0]), "=r"((r)[1]), "=r"((r)[2]), "=r"((r)[3]) : "r"(a))

__device__ __forceinline__ void mma_f16(float* c, const uint32_t* a, const uint32_t* b) {
    asm volatile(
        "mma.sync.aligned.m16n8k16.row.col.f32.f16.f16.f32 "
        "{%0,%1,%2,%3}, {%4,%5,%6,%7}, {%8,%9}, {%0,%1,%2,%3};"
        : "+f"(c[0]), "+f"(c[1]), "+f"(c[2]), "+f"(c[3])
        : "r"(a[0]), "r"(a[1]), "r"(a[2]), "r"(a[3]), "r"(b[0]), "r"(b[1]));
}
__device__ __forceinline__ void mma_bf16(float* c, const uint32_t* a, const uint32_t* b) {
    asm volatile(
        "mma.sync.aligned.m16n8k16.row.col.f32.bf16.bf16.f32 "
        "{%0,%1,%2,%3}, {%4,%5,%6,%7}, {%8,%9}, {%0,%1,%2,%3};"
        : "+f"(c[0]), "+f"(c[1]), "+f"(c[2]), "+f"(c[3])
        : "r"(a[0]), "r"(a[1]), "r"(a[2]), "r"(a[3]), "r"(b[0]), "r"(b[1]));
}

__device__ __forceinline__ uint32_t pack_bf2(float a, float b) {
    __nv_bfloat162 t = __floats2bfloat162_rn(a, b);
    return *reinterpret_cast<uint32_t*>(&t);
}

// ---------------------------------------------------------------------------
// prep: conv A frags + BN1 consts only (tiny, ~24k items). Once per launch.
// ---------------------------------------------------------------------------
__global__ void prep_kernel(
    const float* __restrict__ w1, const float* __restrict__ b1,
    const float* __restrict__ g1, const float* __restrict__ be1,
    const float* __restrict__ m1, const float* __restrict__ v1)
{
    const int idx = blockIdx.x * blockDim.x + threadIdx.x;
    const int stride = gridDim.x * blockDim.x;
    if (idx < NU) {
        const float s = g1[idx] * rsqrtf(v1[idx] + EPSV);
        g_s1[idx] = s;
        g_c1[idx] = (b1[idx] - m1[idx]) * s + be1[idx];
    }
    for (int i = idx; i < 304 * 80; i += stride) {
        const int ul = i / 80;
        const int k  = i % 80;
        const int c  = k / 20;
        const int kk = k - 20 * c;
        float v = 0.f;
        if (ul < NU && kk < FLT) v = w1[ul * 76 + c * FLT + kk];
        const int mt  = ul >> 4, s = k >> 4;
        const int mat = ((ul & 15) >> 3) | (((k & 15) >> 3) << 1);
        const int off = ((((mt * KSTEPS + s) << 2) + mat) << 6)
                        + ((ul & 7) << 3) + (k & 7);
        g_A[off] = __float2half_rn(v);
    }
}

// conv epilogue: 2 pools -> pooled max -> BN+exp -> packed bf16 hi/lo frag
// stored to SMEM staging [u 0..303][wid] (pad rows skipped by the copy).
#define EPI_PAIR(ACC, MT) do {                                                 \
    float cb[2];                                                               \
    _Pragma("unroll") for (int pp = 0; pp < 2; pp++) {                         \
        float mA = fmaxf((ACC)[pp][0], (ACC)[pp][1]);                          \
        float mB = fmaxf((ACC)[pp][2], (ACC)[pp][3]);                          \
        mA = fmaxf(mA, __shfl_xor_sync(0xFFFFFFFFu, mA, 1));                   \
        mB = fmaxf(mB, __shfl_xor_sync(0xFFFFFFFFu, mB, 1));                   \
        float c0 = (lane & 1) ? mB : mA;                                       \
        cb[pp] = fmaxf(c0, __shfl_xor_sync(0xFFFFFFFFu, c0, 2));               \
    }                                                                          \
    if ((lane & 2) == 0) {                                                     \
        const int u = (MT) * 16 + (lane >> 2) + ((lane & 1) << 3);             \
        const float y0 = __expf(fmaf(cb[0], s1s[u], c1s[u]));                  \
        const float y1 = __expf(fmaf(cb[1], s1s[u], c1s[u]));                  \
        const float h0 = __bfloat162float(__float2bfloat16(y0));               \
        const float h1 = __bfloat162float(__float2bfloat16(y1));               \
        uint2 v;                                                               \
        v.x = pack_bf2(y0, y1);                                                \
        v.y = pack_bf2(y0 - h0, y1 - h1);                                      \
        *reinterpret_cast<uint2*>(smem + SST + (u * 14 + wid) * 8) = v;        \
    }                                                                          \
} while (0)

// ---------------------------------------------------------------------------
// Kernel A: conv as warp-HMMA GEMM (fp16), direct-LDS B frags, smem-staged
// y transpose. TAIL: each CTA builds its 1/256 slice of the w2 fragment
// layout (bandwidth work hidden under other CTAs' compute).
// ---------------------------------------------------------------------------
__global__ __launch_bounds__(CTH, 2) void conv_mma_kernel(
    const float* __restrict__ x, const float* __restrict__ w2)
{
    extern __shared__ __align__(128) char smem[];
    const uint32_t sb = smem_u32(smem);

    const int tid  = threadIdx.x;
    const int wid  = tid >> 5;
    const int lane = tid & 31;
    const int b    = blockIdx.x;

    float* s1s = reinterpret_cast<float*>(smem + SBN_S);
    float* c1s = reinterpret_cast<float*>(smem + SBN_C);

    {
        const uint4* src = reinterpret_cast<const uint4*>(g_A);
        uint4* dst = reinterpret_cast<uint4*>(smem + SA);
        for (int i = tid; i < ASZ / 16; i += CTH) dst[i] = src[i];
    }
    if (tid < 304) {                       // pad rows get harmless values
        const int uu = (tid < NU) ? tid : (NU - 1);
        s1s[tid] = g_s1[uu];
        c1s[tid] = g_c1[uu];
    }

    {
        const float* xg = x + (size_t)b * (4 * LIN);
        __half2* xe = reinterpret_cast<__half2*>(smem + SXT);
        __half2* xo = reinterpret_cast<__half2*>(smem + SXT + XTSZ);
#pragma unroll
        for (int c = 0; c < 4; c++) {
            for (int t = tid; t < 312; t += CTH) {
                const int p0 = 2 * t;
                const float f0 = (p0     < LIN) ? xg[c * LIN + p0]     : 0.f;
                const float f1 = (p0 + 1 < LIN) ? xg[c * LIN + p0 + 1] : 0.f;
                const float f2 = (p0 + 2 < LIN) ? xg[c * LIN + p0 + 2] : 0.f;
                xe[c * 312 + t] = __halves2half2(__float2half_rn(f0), __float2half_rn(f1));
                xo[c * 312 + t] = __halves2half2(__float2half_rn(f1), __float2half_rn(f2));
            }
        }
    }
    __syncthreads();

    const uint32_t aBase = sb + SA + lane * 16;
    const int q    = lane & 3;
    const int slot = lane >> 2;
    const int jj   = (slot == 7) ? 0 : slot;

#pragma unroll 1
    for (int rnd = 0; rnd < ROUNDS; rnd++) {
        const int p0 = rnd * (WARPS * PPW) + wid * PPW;

        uint32_t bfr[PPW][KSTEPS][2];
#pragma unroll
        for (int pp = 0; pp < PPW; pp++) {
            const int np = 7 * (p0 + pp) + jj;
#pragma unroll
            for (int s = 0; s < KSTEPS; s++) {
#pragma unroll
                for (int h = 0; h < 2; h++) {
                    const int k  = 16 * s + 8 * h + 2 * q;
                    const int c  = k / 20;
                    const int kk = k - 20 * c;
                    const int o  = np + kk;
                    const uint32_t addr = sb + SXT + (uint32_t)(o & 1) * XTSZ
                                        + (uint32_t)(c * 1248 + ((o >> 1) << 2));
                    asm volatile("ld.shared.b32 %0, [%1];"
                                 : "=r"(bfr[pp][s][h]) : "r"(addr));
                }
            }
        }

#pragma unroll 1
        for (int mt = 0; mt < MTILES; mt++) {
            float acc[PPW][4];
#pragma unroll
            for (int pp = 0; pp < PPW; pp++)
#pragma unroll
                for (int z = 0; z < 4; z++) acc[pp][z] = 0.f;

            uint32_t a[4];
#pragma unroll
            for (int s = 0; s < KSTEPS; s++) {
                LDSM4(a, aBase + (mt * KSTEPS + s) * 512);
                mma_f16(acc[0], a, bfr[0][s]);
                mma_f16(acc[1], a, bfr[1][s]);
            }
            EPI_PAIR(acc, mt);
        }

        // --- coalesced dump: staging [u][14] -> g_yA [u][b][fp0+fp] ---
        __syncthreads();
        {
            const int fp0 = rnd * WARPS;   // 14 f-pairs this round
            for (int i = tid; i < NU * 7; i += CTH) {
                const int u   = i / 7;
                const int fp2 = i % 7;
                const uint4 v = *reinterpret_cast<const uint4*>(
                    smem + SST + (u * 14 + 2 * fp2) * 8);
                *reinterpret_cast<uint4*>(
                    g_yA + ((size_t)u * BATCH + b) * 48 + fp0 + 2 * fp2) = v;
            }
        }
        __syncthreads();
    }

    // --- TAIL: build this CTA's 1/256 slice of the w2 fragment layout ---
    {
        const int base = b * W2SLC;
        for (int j = tid; j < W2SLC; j += CTH) {
            const int i    = base + j;
            const int lane2= i & 31;
            const int rg   = (i >> 5) & 1;
            const int ks   = (i >> 6) % MKS;
            const int nt   = (i / (MKS * 64)) % MNT;
            const int u    = i / W2FSL;
            const int o    = nt * 8 + (lane2 >> 2);
            const int k0   = 16 * ks + 2 * (lane2 & 3) + 8 * rg;
            float v0 = 0.f, v1 = 0.f;
            if (o < HID) {
                if (k0     < LP) v0 = w2[((size_t)u * HID + o) * LP + k0];
                if (k0 + 1 < LP) v1 = w2[((size_t)u * HID + o) * LP + k0 + 1];
            }
            const float h0 = __bfloat162float(__float2bfloat16(v0));
            const float h1 = __bfloat162float(__float2bfloat16(v1));
            uint2 r;
            r.x = pack_bf2(v0, v1);
            r.y = pack_bf2(v0 - h0, v1 - h1);
            g_w2f[i] = r;
        }
    }
}

// ---------------------------------------------------------------------------
// Kernel B: per-unit MLP GEMM via bf16 3-pass HMMA. (proven)
// ---------------------------------------------------------------------------
__global__ __launch_bounds__(256, 2) void unit_mlp_mma(
    const float* __restrict__ b2, const float* __restrict__ g2,
    const float* __restrict__ be2,const float* __restrict__ m2,
    const float* __restrict__ v2, const float* __restrict__ w3,
    const float* __restrict__ b3, const float* __restrict__ g3,
    const float* __restrict__ be3,const float* __restrict__ m3,
    const float* __restrict__ v3)
{
    __shared__ __align__(16) uint2 w2s[W2FSL];          // 39936 B
    __shared__ float s2s[HID], c2s[HID], w3s[HID];

    const int u    = blockIdx.x;
    const int tid  = threadIdx.x;
    const int wid  = tid >> 5;
    const int lane = tid & 31;
    const int g    = lane >> 2;
    const int q    = lane & 3;

    {
        const uint4* src = reinterpret_cast<const uint4*>(g_w2f + (size_t)u * W2FSL);
        uint4* dst = reinterpret_cast<uint4*>(w2s);
        for (int i = tid; i < W2FSL / 2; i += 256) dst[i] = src[i];
    }
    if (tid < HID) {
        const int idx = u * HID + tid;
        const float s = g2[idx] * rsqrtf(v2[idx] + EPSV);
        s2s[tid] = s;
        c2s[tid] = (b2[idx] - m2[idx]) * s + be2[idx];
        w3s[tid] = w3[idx];
    }
    __syncthreads();

#pragma unroll 1
    for (int half = 0; half < 2; half++) {
        const int bt = wid + 8 * half;

        uint32_t ah[MKS][4], al[MKS][4];
        const uint2* yA = g_yA + ((size_t)u * BATCH + bt * 16) * 48;
#pragma unroll
        for (int ks = 0; ks < MKS; ks++) {
            uint2 t0 = yA[(size_t)(g    ) * 48 + 8 * ks + q    ];
            uint2 t1 = yA[(size_t)(g + 8) * 48 + 8 * ks + q    ];
            uint2 t2 = yA[(size_t)(g    ) * 48 + 8 * ks + q + 4];
            uint2 t3 = yA[(size_t)(g + 8) * 48 + 8 * ks + q + 4];
            ah[ks][0] = t0.x; al[ks][0] = t0.y;
            ah[ks][1] = t1.x; al[ks][1] = t1.y;
            ah[ks][2] = t2.x; al[ks][2] = t2.y;
            ah[ks][3] = t3.x; al[ks][3] = t3.y;
        }

        float zp0 = 0.f, zp1 = 0.f;
#pragma unroll 1
        for (int nt = 0; nt < MNT; nt++) {
            uint32_t bh[MKS][2], bl[MKS][2];
            const uint2* wf2 = w2s + (nt * MKS * 2) * 32 + lane;
#pragma unroll
            for (int ks = 0; ks < MKS; ks++) {
                uint2 r0 = wf2[(ks * 2    ) * 32];
                uint2 r1 = wf2[(ks * 2 + 1) * 32];
                bh[ks][0] = r0.x; bl[ks][0] = r0.y;
                bh[ks][1] = r1.x; bl[ks][1] = r1.y;
            }
            float acc[4] = {0.f, 0.f, 0.f, 0.f};
#pragma unroll
            for (int ks = 0; ks < MKS; ks++) {
                mma_bf16(acc, ah[ks], bh[ks]);
                mma_bf16(acc, ah[ks], bl[ks]);
                mma_bf16(acc, al[ks], bh[ks]);
            }
            const int o0 = nt * 8 + 2 * q;
            const int o1 = o0 + 1;
            if (o0 < HID) {
                const float s = s2s[o0], c = c2s[o0], w = w3s[o0];
                zp0 = fmaf(fmaxf(fmaf(acc[0], s, c), 0.f), w, zp0);
                zp1 = fmaf(fmaxf(fmaf(acc[2], s, c), 0.f), w, zp1);
            }
            if (o1 < HID) {
                const float s = s2s[o1], c = c2s[o1], w = w3s[o1];
                zp0 = fmaf(fmaxf(fmaf(acc[1], s, c), 0.f), w, zp0);
                zp1 = fmaf(fmaxf(fmaf(acc[3], s, c), 0.f), w, zp1);
            }
        }
        zp0 += __shfl_xor_sync(0xFFFFFFFFu, zp0, 1);
        zp0 += __shfl_xor_sync(0xFFFFFFFFu, zp0, 2);
        zp1 += __shfl_xor_sync(0xFFFFFFFFu, zp1, 1);
        zp1 += __shfl_xor_sync(0xFFFFFFFFu, zp1, 2);
        if (q == 0) {
            const float s3 = g3[u] * rsqrtf(v3[u] + EPSV);
            const float c3 = (b3[u] - m3[u]) * s3 + be3[u];
            g_z[u * BATCH + bt * 16 + g    ] = fmaxf(fmaf(zp0, s3, c3), 0.f);
            g_z[u * BATCH + bt * 16 + g + 8] = fmaxf(fmaf(zp1, s3, c3), 0.f);
        }
    }
}

// ---------------------------------------------------------------------------
// Kernel C1: split-K final linear partials. grid (NCLS, 12), block 256.
// ---------------------------------------------------------------------------
__global__ __launch_bounds__(BATCH) void final_split_kernel(const float* __restrict__ wf)
{
    __shared__ float wfs[25];
    const int c   = blockIdx.x;
    const int sp  = blockIdx.y;
    const int tid = threadIdx.x;

    if (tid < 25) wfs[tid] = wf[c * NU + sp * 25 + tid];
    __syncthreads();

    const float* zp = g_z + (size_t)sp * 25 * BATCH + tid;
    float a0 = 0.f, a1 = 0.f, a2 = 0.f, a3 = 0.f;
#pragma unroll
    for (int j = 0; j < 6; j++) {
        a0 = fmaf(zp[(4 * j    ) * BATCH], wfs[4 * j    ], a0);
        a1 = fmaf(zp[(4 * j + 1) * BATCH], wfs[4 * j + 1], a1);
        a2 = fmaf(zp[(4 * j + 2) * BATCH], wfs[4 * j + 2], a2);
        a3 = fmaf(zp[(4 * j + 3) * BATCH], wfs[4 * j + 3], a3);
    }
    a0 = fmaf(zp[24 * BATCH], wfs[24], a0);
    g_part[(sp * NCLS + c) * BATCH + tid] = (a0 + a1) + (a2 + a3);
}

// ---------------------------------------------------------------------------
// Kernel C2: reduce partials + bias. grid NCLS, block 256.
// ---------------------------------------------------------------------------
__global__ __launch_bounds__(BATCH) void final_reduce_kernel(
    const float* __restrict__ bf, float* __restrict__ out)
{
    const int c   = blockIdx.x;
    const int tid = threadIdx.x;
    float s = bf[c];
#pragma unroll
    for (int sp = 0; sp < FSPL; sp++)
        s += g_part[(sp * NCLS + c) * BATCH + tid];
    out[tid * NCLS + c] = s;
}

// ---------------------------------------------------------------------------
extern "C" void kernel_launch(void* const* d_in, const int* in_sizes, int n_in,
                              void* d_out, int out_size)
{
    const float* x   = (const float*)d_in[0];
    const float* w1  = (const float*)d_in[1];
    const float* b1  = (const float*)d_in[2];
    const float* g1  = (const float*)d_in[3];
    const float* be1 = (const float*)d_in[4];
    const float* m1  = (const float*)d_in[5];
    const float* v1  = (const float*)d_in[6];
    const float* w2  = (const float*)d_in[7];
    const float* b2  = (const float*)d_in[8];
    const float* g2  = (const float*)d_in[9];
    const float* be2 = (const float*)d_in[10];
    const float* m2  = (const float*)d_in[11];
    const float* v2  = (const float*)d_in[12];
    const float* w3  = (const float*)d_in[13];
    const float* b3  = (const float*)d_in[14];
    const float* g3  = (const float*)d_in[15];
    const float* be3 = (const float*)d_in[16];
    const float* m3  = (const float*)d_in[17];
    const float* v3  = (const float*)d_in[18];
    const float* wf  = (const float*)d_in[19];
    const float* bf  = (const float*)d_in[20];
    float* out = (float*)d_out;

    cudaFuncSetAttribute(conv_mma_kernel,
                         cudaFuncAttributeMaxDynamicSharedMemorySize, SMTOT);

    prep_kernel<<<48, 512>>>(w1, b1, g1, be1, m1, v1);
    conv_mma_kernel<<<BATCH, CTH, SMTOT>>>(x, w2);
    unit_mlp_mma<<<NU, 256>>>(b2, g2, be2, m2, v2, w3, b3, g3, be3, m3, v3);
    final_split_kernel<<<dim3(NCLS, FSPL), BATCH>>>(wf);
    final_reduce_kernel<<<NCLS, BATCH>>>(bf, out);
}